// round 13
// baseline (speedup 1.0000x reference)
#include <cuda_runtime.h>
#include <cuda_fp16.h>
#include <cstdint>

#define B_    8
#define CIN   256
#define COUT  256
#define CINFO 256
#define LL    32768
#define CHUNK 32                 // l-positions per chunk
#define NCH   (LL / CHUNK)       // 1024 chunks per batch
#define JPITCH 40                // words per jj row (32 l + 8 pad)
#define KTSZ  (8 * JPITCH)       // 320 words per kt slab
#define BUFW  (16 * KTSZ)        // 5120 words per buffer (20 KB)

// ---------------- device scratch ----------------
__device__ float  g_Ain [B_ * CIN * 2];     // [b][2i + r]
__device__ float  g_Aout[B_ * 2 * COUT];    // [b][r*256 + o]
__device__ __half g_Weff[B_ * COUT * CIN];  // [b][o][i]

// ---------------- helpers ----------------
__device__ __forceinline__ uint32_t pack_f16x2(float lo, float hi) {
    uint32_t r;  // second source -> low half
    asm("cvt.rn.f16x2.f32 %0, %1, %2;" : "=r"(r) : "f"(hi), "f"(lo));
    return r;
}

__device__ __forceinline__ void mma16816(float* c, const uint32_t* A, uint32_t b0, uint32_t b1) {
    asm volatile(
        "mma.sync.aligned.m16n8k16.row.col.f32.f16.f16.f32 "
        "{%0,%1,%2,%3}, {%4,%5,%6,%7}, {%8,%9}, {%0,%1,%2,%3};"
        : "+f"(c[0]), "+f"(c[1]), "+f"(c[2]), "+f"(c[3])
        : "r"(A[0]), "r"(A[1]), "r"(A[2]), "r"(A[3]), "r"(b0), "r"(b1));
}

// ---------------- prologue 1: adapter vectors ----------------
__global__ void lora_adapters_kernel(const float* __restrict__ g_out,
                                     const float* __restrict__ W_ain,
                                     const float* __restrict__ W_aout) {
    __shared__ float4 sg4[CINFO / 4];
    int bx = blockIdx.x;
    int b = bx >> 7;
    int kbase = (bx & 127) * 4;
    if (threadIdx.x < CINFO / 4)
        sg4[threadIdx.x] = ((const float4*)(g_out + b * CINFO))[threadIdx.x];
    __syncthreads();
    int w = threadIdx.x >> 5, lane = threadIdx.x & 31;
    int k = kbase + w;
    const float4* wi = (const float4*)(W_ain  + (size_t)k * CINFO);
    const float4* wo = (const float4*)(W_aout + (size_t)k * CINFO);
    float ai = 0.f, ao = 0.f;
#pragma unroll
    for (int h = 0; h < 2; ++h) {
        int i = lane + 32 * h;
        float4 gv = sg4[i];
        float4 a = wi[i], o = wo[i];
        ai += a.x * gv.x + a.y * gv.y + a.z * gv.z + a.w * gv.w;
        ao += o.x * gv.x + o.y * gv.y + o.z * gv.z + o.w * gv.w;
    }
#pragma unroll
    for (int off = 16; off; off >>= 1) {
        ai += __shfl_xor_sync(0xFFFFFFFFu, ai, off);
        ao += __shfl_xor_sync(0xFFFFFFFFu, ao, off);
    }
    if (lane == 0) {
        g_Ain [b * 512 + k] = ai;
        g_Aout[b * 512 + k] = ao;
    }
}

// ---------------- prologue 2: effective weight (fp16) ----------------
__global__ void lora_weff_kernel(const float* __restrict__ W_main) {
    int o = blockIdx.x, b = blockIdx.y, i = threadIdx.x;
    float wm = W_main[o * CIN + i];
    float a0 = g_Ain [b * 512 + i * 2 + 0];
    float a1 = g_Ain [b * 512 + i * 2 + 1];
    float q0 = g_Aout[b * 512 + o];
    float q1 = g_Aout[b * 512 + COUT + o];
    g_Weff[(size_t)b * (COUT * CIN) + o * CIN + i] = __float2half(wm + q0 * a0 + q1 * a1);
}

// ---------------- main persistent GEMM: 16 warps, M-split ----------------
// 512 threads / 16 warps. Warp w owns cout rows [16w, 16w+16) (ONE m-tile),
// full N=32 (4 n-tiles), full K=256 in registers (A = 64 regs, acc = 16,
// staging = 16 -> ~120 regs/thread; 512 threads fit the RF; occ 25%).
// 64 MMAs/warp/chunk; CTA total 1024 MMAs (same as before).
//
// Per chunk: LDG.128 of chunk c+1 first (staged in regs), MMA block on c,
// pack+STS.128 of c+1 after MMAs (LDG latency hidden), epilogue, 1 barrier.
//
// SMEM word(kt, jj, l) = kt*320 + jj*40 + l. Consumer bank
// (8q + 8nt + gg) mod 32 = full 32-bank permutation for b0 (jj=q) and b1
// (jj=q+4: +160 words = 0 mod 32). STS.128: warp w fills kt slab w; each
// 8-lane phase writes words jj*40 + 4*ll (ll=0..7) -> 8 distinct 16B blocks
// covering all 32 banks. Conflict-free.
__global__ void __launch_bounds__(512, 1)
lora_main_kernel(const float* __restrict__ x, const float* __restrict__ b_main,
                 float* __restrict__ out, int per_batch) {
    extern __shared__ uint32_t sm[];   // 2 * BUFW words = 40 KB
    const int tid = threadIdx.x;
    const int lane = tid & 31;
    const int w = tid >> 5;            // 0..15
    const int cta = blockIdx.x;
    const int b  = cta / per_batch;
    const int jb = cta % per_batch;
    const int s = (jb * NCH) / per_batch;
    const int e = ((jb + 1) * NCH) / per_batch;
    if (s >= e) return;

    const float* xb = x   + (size_t)b * ((size_t)CIN * LL);
    float*       ob = out + (size_t)b * ((size_t)COUT * LL);

    const int obase = w * 16;
    const int gg = lane >> 2;    // 0..7 (MMA row group)
    const int q  = lane & 3;     // 0..3

    // ---- A fragments (Weff rows [16w,16w+16)) resident in registers ----
    uint32_t A[16][4];
    {
        const __half* Wb = g_Weff + (size_t)b * (COUT * CIN);
        const uint32_t* r0 = (const uint32_t*)(Wb + (size_t)(obase + gg)     * CIN);
        const uint32_t* r1 = (const uint32_t*)(Wb + (size_t)(obase + 8 + gg) * CIN);
#pragma unroll
        for (int kt = 0; kt < 16; ++kt) {
            A[kt][0] = r0[kt * 8 + q];
            A[kt][1] = r1[kt * 8 + q];
            A[kt][2] = r0[kt * 8 + 4 + q];
            A[kt][3] = r1[kt * 8 + 4 + q];
        }
    }
    const float bg0 = b_main[obase + gg];
    const float bg1 = b_main[obase + 8 + gg];

    // LDG staging: warp w loads x rows [16w, 16w+16) = its own kt slab.
    // lane = 8*pp + ll: pp = lane>>3 (row-pair phase), ll = lane&7 (l/4 pos).
    // Thread loads pairs p = pp + 4j (j=0,1), float4 at l = ll*4.
    float4 sa[2], sb[2];
    const int c4 = (lane & 7) * 4;
    const int pp = lane >> 3;

    auto ldg_issue = [&](int chunk) {
        const float* base = xb + (size_t)chunk * CHUNK + c4;
#pragma unroll
        for (int j = 0; j < 2; ++j) {
            int row0 = w * 16 + 2 * (pp + 4 * j);
            sa[j] = *(const float4*)(base + (size_t)row0 * LL);
            sb[j] = *(const float4*)(base + (size_t)(row0 + 1) * LL);
        }
    };

    auto pack_sts = [&](int bufsel) {
        uint32_t* dst = sm + bufsel * BUFW + w * KTSZ;
#pragma unroll
        for (int j = 0; j < 2; ++j) {
            int jj = pp + 4 * j;
            uint4 v;
            v.x = pack_f16x2(sa[j].x, sb[j].x);
            v.y = pack_f16x2(sa[j].y, sb[j].y);
            v.z = pack_f16x2(sa[j].z, sb[j].z);
            v.w = pack_f16x2(sa[j].w, sb[j].w);
            *(uint4*)(dst + jj * JPITCH + c4) = v;
        }
    };

    ldg_issue(s);
    pack_sts(0);
    __syncthreads();

    for (int c = s; c < e; ++c) {
        const int cb = (c - s) & 1;
        const bool more = (c + 1) < e;
        if (more) ldg_issue(c + 1);   // staged across the MMA block

        float acc[4][4];
#pragma unroll
        for (int nt = 0; nt < 4; ++nt)
#pragma unroll
            for (int r = 0; r < 4; ++r) acc[nt][r] = 0.f;

        const uint32_t* buf = sm + cb * BUFW;
#pragma unroll
        for (int nt = 0; nt < 4; ++nt) {
            const int l = nt * 8 + gg;
            const uint32_t* p0 = buf + q * JPITCH + l;          // jj = q
            const uint32_t* p1 = buf + (q + 4) * JPITCH + l;    // jj = q+4
#pragma unroll
            for (int kt = 0; kt < 16; ++kt) {
                uint32_t b0 = p0[kt * KTSZ];
                uint32_t b1 = p1[kt * KTSZ];
                mma16816(acc[nt], A[kt], b0, b1);
            }
        }

        if (more) pack_sts(cb ^ 1);   // pack AFTER MMAs: LDG latency hidden

        // epilogue: bias + coalesced float2 stores
        {
            const size_t lc = (size_t)c * CHUNK + 2 * q;
            float* o0 = ob + (size_t)(obase + gg)     * LL + lc;
            float* o1 = ob + (size_t)(obase + 8 + gg) * LL + lc;
#pragma unroll
            for (int nt = 0; nt < 4; ++nt) {
                *(float2*)(o0 + nt * 8) = make_float2(acc[nt][0] + bg0, acc[nt][1] + bg0);
                *(float2*)(o1 + nt * 8) = make_float2(acc[nt][2] + bg1, acc[nt][3] + bg1);
            }
        }
        __syncthreads();
    }
}

// ---------------- launch ----------------
extern "C" void kernel_launch(void* const* d_in, const int* in_sizes, int n_in,
                              void* d_out, int out_size) {
    const float* x      = (const float*)d_in[0];
    const float* g_out  = (const float*)d_in[1];
    const float* W_main = (const float*)d_in[2];
    const float* b_main = (const float*)d_in[3];
    const float* W_ain  = (const float*)d_in[4];
    const float* W_aout = (const float*)d_in[5];
    float* out = (float*)d_out;

    int dev = 0, sms = 148;
    cudaGetDevice(&dev);
    cudaDeviceGetAttribute(&sms, cudaDevAttrMultiProcessorCount, dev);
    int per_batch = sms / B_;
    if (per_batch < 1) per_batch = 1;
    if (per_batch > NCH) per_batch = NCH;

    size_t smem = 2ull * BUFW * sizeof(uint32_t);  // 40 KB
    cudaFuncSetAttribute(lora_main_kernel, cudaFuncAttributeMaxDynamicSharedMemorySize, (int)smem);

    lora_adapters_kernel<<<B_ * 128, 128>>>(g_out, W_ain, W_aout);
    lora_weff_kernel<<<dim3(COUT, B_), CIN>>>(W_main);
    lora_main_kernel<<<per_batch * B_, 512, smem>>>(x, b_main, out, per_batch);
}

// round 15
// speedup vs baseline: 1.0911x; 1.0911x over previous
#include <cuda_runtime.h>
#include <cuda_fp16.h>
#include <cstdint>

#define B_    8
#define CIN   256
#define COUT  256
#define CINFO 256
#define LL    32768
#define CHUNK 32                 // l-positions per chunk
#define NCH   (LL / CHUNK)       // 1024 chunks per batch
#define JPITCH 40                // words per jj row (32 l + 8 pad)
#define KTSZ  (8 * JPITCH)       // 320 words per kt slab
#define BUFW  (16 * KTSZ)        // 5120 words per buffer (20 KB)

// ---------------- device scratch ----------------
__device__ float  g_Ain [B_ * CIN * 2];     // [b][2i + r]
__device__ float  g_Aout[B_ * 2 * COUT];    // [b][r*256 + o]
__device__ __half g_Weff[B_ * COUT * CIN];  // [b][o][i]

// ---------------- helpers ----------------
__device__ __forceinline__ uint32_t pack_f16x2(float lo, float hi) {
    uint32_t r;  // second source -> low half
    asm("cvt.rn.f16x2.f32 %0, %1, %2;" : "=r"(r) : "f"(hi), "f"(lo));
    return r;
}

__device__ __forceinline__ void mma16816(float* c, const uint32_t* A, uint32_t b0, uint32_t b1) {
    asm volatile(
        "mma.sync.aligned.m16n8k16.row.col.f32.f16.f16.f32 "
        "{%0,%1,%2,%3}, {%4,%5,%6,%7}, {%8,%9}, {%0,%1,%2,%3};"
        : "+f"(c[0]), "+f"(c[1]), "+f"(c[2]), "+f"(c[3])
        : "r"(A[0]), "r"(A[1]), "r"(A[2]), "r"(A[3]), "r"(b0), "r"(b1));
}

// ---------------- prologue 1: adapter vectors ----------------
__global__ void lora_adapters_kernel(const float* __restrict__ g_out,
                                     const float* __restrict__ W_ain,
                                     const float* __restrict__ W_aout) {
    __shared__ float4 sg4[CINFO / 4];
    int bx = blockIdx.x;
    int b = bx >> 7;
    int kbase = (bx & 127) * 4;
    if (threadIdx.x < CINFO / 4)
        sg4[threadIdx.x] = ((const float4*)(g_out + b * CINFO))[threadIdx.x];
    __syncthreads();
    int w = threadIdx.x >> 5, lane = threadIdx.x & 31;
    int k = kbase + w;
    const float4* wi = (const float4*)(W_ain  + (size_t)k * CINFO);
    const float4* wo = (const float4*)(W_aout + (size_t)k * CINFO);
    float ai = 0.f, ao = 0.f;
#pragma unroll
    for (int h = 0; h < 2; ++h) {
        int i = lane + 32 * h;
        float4 gv = sg4[i];
        float4 a = wi[i], o = wo[i];
        ai += a.x * gv.x + a.y * gv.y + a.z * gv.z + a.w * gv.w;
        ao += o.x * gv.x + o.y * gv.y + o.z * gv.z + o.w * gv.w;
    }
#pragma unroll
    for (int off = 16; off; off >>= 1) {
        ai += __shfl_xor_sync(0xFFFFFFFFu, ai, off);
        ao += __shfl_xor_sync(0xFFFFFFFFu, ao, off);
    }
    if (lane == 0) {
        g_Ain [b * 512 + k] = ai;
        g_Aout[b * 512 + k] = ao;
    }
}

// ---------------- prologue 2: effective weight (fp16) ----------------
__global__ void lora_weff_kernel(const float* __restrict__ W_main) {
    int o = blockIdx.x, b = blockIdx.y, i = threadIdx.x;
    float wm = W_main[o * CIN + i];
    float a0 = g_Ain [b * 512 + i * 2 + 0];
    float a1 = g_Ain [b * 512 + i * 2 + 1];
    float q0 = g_Aout[b * 512 + o];
    float q1 = g_Aout[b * 512 + COUT + o];
    g_Weff[(size_t)b * (COUT * CIN) + o * CIN + i] = __float2half(wm + q0 * a0 + q1 * a1);
}

// ---------------- main persistent GEMM (R7 champion + ILP reorder) ----------------
// Identical to the 127.8us kernel except the MMA loop:
//   kt-OUTER / nt-INNER -> 8 independent accumulator chains (same-chain
//   reuse spacing 8 MMAs = 64 cyc > HMMA latency), with kt+1's 8 B-words
//   LDS-prefetched during kt's MMAs (29-cyc LDS latency hidden).
// SMEM word(kt, jj, l) = kt*320 + jj*40 + l. Consumer bank (8q + l) mod 32:
// full permutation for b0 (jj=q) and b1 (jj=q+4); STS.128 phases cover all
// 32 banks. Conflict-free (unchanged from R7).
__global__ void __launch_bounds__(256, 1)
lora_main_kernel(const float* __restrict__ x, const float* __restrict__ b_main,
                 float* __restrict__ out, int per_batch) {
    extern __shared__ uint32_t sm[];   // 2 * BUFW words = 40 KB
    const int tid = threadIdx.x;
    const int lane = tid & 31;
    const int w = tid >> 5;            // 0..7
    const int cta = blockIdx.x;
    const int b  = cta / per_batch;
    const int jb = cta % per_batch;
    const int s = (jb * NCH) / per_batch;
    const int e = ((jb + 1) * NCH) / per_batch;
    if (s >= e) return;

    const float* xb = x   + (size_t)b * ((size_t)CIN * LL);
    float*       ob = out + (size_t)b * ((size_t)COUT * LL);

    const int obase = w * 32;
    const int gg = lane >> 2;    // 0..7 (MMA row group)
    const int q  = lane & 3;     // 0..3

    // ---- A fragments (Weff) resident in registers ----
    uint32_t A0[16][4], A1[16][4];
    {
        const __half* Wb = g_Weff + (size_t)b * (COUT * CIN);
        const uint32_t* r00 = (const uint32_t*)(Wb + (size_t)(obase + gg)      * CIN);
        const uint32_t* r01 = (const uint32_t*)(Wb + (size_t)(obase + gg + 8)  * CIN);
        const uint32_t* r10 = (const uint32_t*)(Wb + (size_t)(obase + 16 + gg) * CIN);
        const uint32_t* r11 = (const uint32_t*)(Wb + (size_t)(obase + 24 + gg) * CIN);
#pragma unroll
        for (int kt = 0; kt < 16; ++kt) {
            A0[kt][0] = r00[kt * 8 + q];
            A0[kt][1] = r01[kt * 8 + q];
            A0[kt][2] = r00[kt * 8 + 4 + q];
            A0[kt][3] = r01[kt * 8 + 4 + q];
            A1[kt][0] = r10[kt * 8 + q];
            A1[kt][1] = r11[kt * 8 + q];
            A1[kt][2] = r10[kt * 8 + 4 + q];
            A1[kt][3] = r11[kt * 8 + 4 + q];
        }
    }
    const float bg00 = b_main[obase + gg];
    const float bg01 = b_main[obase + 8 + gg];
    const float bg10 = b_main[obase + 16 + gg];
    const float bg11 = b_main[obase + 24 + gg];

    // LDG staging: thread loads row-pair p = (lane>>3) + 4j, float4 at l = (lane&7)*4
    float4 sa[4], sb[4];
    const int c4 = (lane & 7) * 4;
    const int ph = lane >> 3;

    auto ldg_issue = [&](int chunk) {
        const float* base = xb + (size_t)chunk * CHUNK + c4;
#pragma unroll
        for (int j = 0; j < 4; ++j) {
            int row0 = w * 32 + 2 * (ph + 4 * j);
            sa[j] = *(const float4*)(base + (size_t)row0 * LL);
            sb[j] = *(const float4*)(base + (size_t)(row0 + 1) * LL);
        }
    };

    auto pack_sts = [&](int bufsel) {
        uint32_t* dst = sm + bufsel * BUFW;
#pragma unroll
        for (int j = 0; j < 4; ++j) {
            int p  = ph + 4 * j;
            int kt = 2 * w + (p >> 3);
            int jj = p & 7;
            uint4 v;
            v.x = pack_f16x2(sa[j].x, sb[j].x);
            v.y = pack_f16x2(sa[j].y, sb[j].y);
            v.z = pack_f16x2(sa[j].z, sb[j].z);
            v.w = pack_f16x2(sa[j].w, sb[j].w);
            *(uint4*)(dst + kt * KTSZ + jj * JPITCH + c4) = v;
        }
    };

    ldg_issue(s);
    pack_sts(0);
    __syncthreads();

    for (int c = s; c < e; ++c) {
        const int cb = (c - s) & 1;
        const bool more = (c + 1) < e;
        if (more) ldg_issue(c + 1);   // staged across the MMA block

        float acc0[4][4], acc1[4][4];
#pragma unroll
        for (int nt = 0; nt < 4; ++nt)
#pragma unroll
            for (int r = 0; r < 4; ++r) { acc0[nt][r] = 0.f; acc1[nt][r] = 0.f; }

        const uint32_t* buf = sm + cb * BUFW;

        // kt-outer / nt-inner with double-buffered LDS prefetch
        uint32_t b0v[2][4], b1v[2][4];
#pragma unroll
        for (int nt = 0; nt < 4; ++nt) {
            const int l = nt * 8 + gg;
            b0v[0][nt] = buf[q * JPITCH + l];             // kt = 0, jj = q
            b1v[0][nt] = buf[(q + 4) * JPITCH + l];       // kt = 0, jj = q+4
        }
#pragma unroll
        for (int kt = 0; kt < 16; ++kt) {
            const int cur = kt & 1, nxt = cur ^ 1;
            if (kt < 15) {
                const uint32_t* nbuf = buf + (kt + 1) * KTSZ;
#pragma unroll
                for (int nt = 0; nt < 4; ++nt) {
                    const int l = nt * 8 + gg;
                    b0v[nxt][nt] = nbuf[q * JPITCH + l];
                    b1v[nxt][nt] = nbuf[(q + 4) * JPITCH + l];
                }
            }
#pragma unroll
            for (int nt = 0; nt < 4; ++nt) {
                mma16816(acc0[nt], A0[kt], b0v[cur][nt], b1v[cur][nt]);
                mma16816(acc1[nt], A1[kt], b0v[cur][nt], b1v[cur][nt]);
            }
        }

        if (more) pack_sts(cb ^ 1);   // pack AFTER MMAs: LDG latency hidden

        // epilogue: bias + coalesced float2 stores
        {
            const size_t lc = (size_t)c * CHUNK + 2 * q;
            float* o00 = ob + (size_t)(obase + gg)      * LL + lc;
            float* o01 = ob + (size_t)(obase + gg + 8)  * LL + lc;
            float* o10 = ob + (size_t)(obase + 16 + gg) * LL + lc;
            float* o11 = ob + (size_t)(obase + 24 + gg) * LL + lc;
#pragma unroll
            for (int nt = 0; nt < 4; ++nt) {
                *(float2*)(o00 + nt * 8) = make_float2(acc0[nt][0] + bg00, acc0[nt][1] + bg00);
                *(float2*)(o01 + nt * 8) = make_float2(acc0[nt][2] + bg01, acc0[nt][3] + bg01);
                *(float2*)(o10 + nt * 8) = make_float2(acc1[nt][0] + bg10, acc1[nt][1] + bg10);
                *(float2*)(o11 + nt * 8) = make_float2(acc1[nt][2] + bg11, acc1[nt][3] + bg11);
            }
        }
        __syncthreads();
    }
}

// ---------------- launch ----------------
extern "C" void kernel_launch(void* const* d_in, const int* in_sizes, int n_in,
                              void* d_out, int out_size) {
    const float* x      = (const float*)d_in[0];
    const float* g_out  = (const float*)d_in[1];
    const float* W_main = (const float*)d_in[2];
    const float* b_main = (const float*)d_in[3];
    const float* W_ain  = (const float*)d_in[4];
    const float* W_aout = (const float*)d_in[5];
    float* out = (float*)d_out;

    int dev = 0, sms = 148;
    cudaGetDevice(&dev);
    cudaDeviceGetAttribute(&sms, cudaDevAttrMultiProcessorCount, dev);
    int per_batch = sms / B_;
    if (per_batch < 1) per_batch = 1;
    if (per_batch > NCH) per_batch = NCH;

    size_t smem = 2ull * BUFW * sizeof(uint32_t);  // 40 KB
    cudaFuncSetAttribute(lora_main_kernel, cudaFuncAttributeMaxDynamicSharedMemorySize, (int)smem);

    lora_adapters_kernel<<<B_ * 128, 128>>>(g_out, W_ain, W_aout);
    lora_weff_kernel<<<dim3(COUT, B_), CIN>>>(W_main);
    lora_main_kernel<<<per_batch * B_, 256, smem>>>(x, b_main, out, per_batch);
}